// round 4
// baseline (speedup 1.0000x reference)
#include <cuda_runtime.h>
#include <math.h>

#define NODES 1024
#define FDIM  64
#define HID   32
#define HH    16        // HID/2 (packed f32x2 lanes)
#define EDGES 65536
#define BI    16
#define BJ    64

// Precomputed per-node terms: A = x @ W1[0:64] + b1 ; B = x @ W1[64:128]
__device__ float g_A[NODES * HID];
__device__ float g_B[NODES * HID];

// ---------------- packed f32x2 helpers (SASS FFMA2 path) ----------------
__device__ __forceinline__ unsigned long long pack2(float lo, float hi) {
    unsigned long long r;
    asm("mov.b64 %0, {%1, %2};" : "=l"(r) : "f"(lo), "f"(hi));
    return r;
}
__device__ __forceinline__ void unpack2(unsigned long long v, float& lo, float& hi) {
    asm("mov.b64 {%0, %1}, %2;" : "=f"(lo), "=f"(hi) : "l"(v));
}
__device__ __forceinline__ unsigned long long ffma2(unsigned long long a,
                                                    unsigned long long b,
                                                    unsigned long long c) {
    unsigned long long d;
    asm("fma.rn.f32x2 %0, %1, %2, %3;" : "=l"(d) : "l"(a), "l"(b), "l"(c));
    return d;
}

__device__ __forceinline__ float sigmoidf_(float x) {
    return 1.0f / (1.0f + expf(-x));
}

// ---------------- prep: per-node A/B ----------------
__global__ void prep_kernel(const float* __restrict__ x,
                            const float* __restrict__ W1,
                            const float* __restrict__ b1) {
    __shared__ float xr[FDIM];
    int node = blockIdx.x;
    int t = threadIdx.x;                 // 64 threads
    xr[t] = x[node * FDIM + t];
    __syncthreads();
    int h = t & 31;
    const float* W = W1 + ((t < 32) ? 0 : FDIM * HID);   // rows [0:64] or [64:128]
    float acc = (t < 32) ? b1[h] : 0.0f;
#pragma unroll
    for (int f = 0; f < FDIM; f++)
        acc = fmaf(xr[f], W[f * HID + h], acc);
    if (t < 32) g_A[node * HID + h] = acc;
    else        g_B[node * HID + h] = acc;
}

// ---------------- dense all-pairs branch ----------------
__global__ __launch_bounds__(256, 1)
void dense_kernel(const float* __restrict__ x,
                  const float* __restrict__ W1,
                  const float* __restrict__ W2,
                  const float* __restrict__ b2,
                  float* __restrict__ P) {
    __shared__ float s_xi[BI][FDIM + 1];
    __shared__ float s_xj[BJ][FDIM + 1];
    __shared__ unsigned long long s_Wc[FDIM][HH];   // W1 rows [128:192], |diff| block
    __shared__ unsigned long long s_Wd[FDIM][HH];   // W1 rows [192:256], prod block
    __shared__ float s_W2[HID];

    int t  = threadIdx.x;
    int i0 = blockIdx.x * BI;
    int j0 = blockIdx.y * BJ;

    for (int k = t; k < BI * FDIM; k += 256)
        s_xi[k >> 6][k & 63] = x[(i0 + (k >> 6)) * FDIM + (k & 63)];
    for (int k = t; k < BJ * FDIM; k += 256)
        s_xj[k >> 6][k & 63] = x[(j0 + (k >> 6)) * FDIM + (k & 63)];
    for (int k = t; k < FDIM * HH; k += 256) {
        int f = k >> 4, hh = k & 15;
        float2 c = ((const float2*)(W1 + (128 + f) * HID))[hh];
        float2 d = ((const float2*)(W1 + (192 + f) * HID))[hh];
        s_Wc[f][hh] = pack2(c.x, c.y);
        s_Wd[f][hh] = pack2(d.x, d.y);
    }
    if (t < HID) s_W2[t] = W2[t];
    __syncthreads();

    int il = t >> 4;       // 0..15  (i within tile)
    int jl = t & 15;       // 0..15  (j's: jl + 16*p, p=0..3)
    int i  = i0 + il;

    unsigned long long acc[4][HH];
#pragma unroll
    for (int p = 0; p < 4; p++) {
        const float* Ar = g_A + i * HID;
        const float* Br = g_B + (j0 + jl + 16 * p) * HID;
#pragma unroll
        for (int hh = 0; hh < HH; hh++)
            acc[p][hh] = pack2(Ar[2 * hh] + Br[2 * hh], Ar[2 * hh + 1] + Br[2 * hh + 1]);
    }

#pragma unroll 4
    for (int f = 0; f < FDIM; f++) {
        float xiv = s_xi[il][f];
        unsigned long long dd[4], pm[4];
#pragma unroll
        for (int p = 0; p < 4; p++) {
            float xjv = s_xj[jl + 16 * p][f];
            float ad = fabsf(xiv - xjv);
            float pr = xiv * xjv;
            dd[p] = pack2(ad, ad);
            pm[p] = pack2(pr, pr);
        }
#pragma unroll
        for (int hh = 0; hh < HH; hh++) {
            unsigned long long wc = s_Wc[f][hh];
            unsigned long long wd = s_Wd[f][hh];
#pragma unroll
            for (int p = 0; p < 4; p++) {
                acc[p][hh] = ffma2(dd[p], wc, acc[p][hh]);
                acc[p][hh] = ffma2(pm[p], wd, acc[p][hh]);
            }
        }
    }

    float bias2 = b2[0];
#pragma unroll
    for (int p = 0; p < 4; p++) {
        float logit = bias2;
#pragma unroll
        for (int hh = 0; hh < HH; hh++) {
            float lo, hi;
            unpack2(acc[p][hh], lo, hi);
            logit += fmaxf(lo, 0.0f) * s_W2[2 * hh] + fmaxf(hi, 0.0f) * s_W2[2 * hh + 1];
        }
        P[i * NODES + j0 + jl + 16 * p] = sigmoidf_(logit);
    }
}

// ---------------- sparse edge branch ----------------
__global__ __launch_bounds__(256)
void edge_kernel(const float* __restrict__ x,
                 const int* __restrict__ ei,   // int32! (JAX x64 disabled)
                 const float* __restrict__ W1,
                 const float* __restrict__ W2,
                 const float* __restrict__ b2,
                 float* __restrict__ probs,
                 float* __restrict__ acts) {
    __shared__ unsigned long long s_Wc[FDIM][HH];
    __shared__ unsigned long long s_Wd[FDIM][HH];
    __shared__ float s_W2[HID];
    int t = threadIdx.x;
    for (int k = t; k < FDIM * HH; k += 256) {
        int f = k >> 4, hh = k & 15;
        float2 c = ((const float2*)(W1 + (128 + f) * HID))[hh];
        float2 d = ((const float2*)(W1 + (192 + f) * HID))[hh];
        s_Wc[f][hh] = pack2(c.x, c.y);
        s_Wd[f][hh] = pack2(d.x, d.y);
    }
    if (t < HID) s_W2[t] = W2[t];
    __syncthreads();

    int e = blockIdx.x * 256 + t;
    int s = ei[e];
    int d = ei[EDGES + e];

    unsigned long long acc[HH];
    {
        const float* Ar = g_A + s * HID;
        const float* Br = g_B + d * HID;
#pragma unroll
        for (int hh = 0; hh < HH; hh++)
            acc[hh] = pack2(Ar[2 * hh] + Br[2 * hh], Ar[2 * hh + 1] + Br[2 * hh + 1]);
    }

    const float4* xs4 = (const float4*)(x + s * FDIM);
    const float4* xd4 = (const float4*)(x + d * FDIM);
#pragma unroll 4
    for (int c = 0; c < FDIM / 4; c++) {
        float4 a = __ldg(xs4 + c);
        float4 b = __ldg(xd4 + c);
        float av[4] = {a.x, a.y, a.z, a.w};
        float bv[4] = {b.x, b.y, b.z, b.w};
#pragma unroll
        for (int u = 0; u < 4; u++) {
            int f = c * 4 + u;
            float ad = fabsf(av[u] - bv[u]);
            float pr = av[u] * bv[u];
            unsigned long long dd = pack2(ad, ad);
            unsigned long long pm = pack2(pr, pr);
#pragma unroll
            for (int hh = 0; hh < HH; hh++) {
                acc[hh] = ffma2(dd, s_Wc[f][hh], acc[hh]);
                acc[hh] = ffma2(pm, s_Wd[f][hh], acc[hh]);
            }
        }
    }

    float logit = b2[0];
#pragma unroll
    for (int hh = 0; hh < HH; hh++) {
        float lo, hi;
        unpack2(acc[hh], lo, hi);
        logit += fmaxf(lo, 0.0f) * s_W2[2 * hh] + fmaxf(hi, 0.0f) * s_W2[2 * hh + 1];
    }
    float prob = sigmoidf_(logit);
    probs[e] = prob;
    acts[e]  = (prob > 0.4f) ? 1.0f : 0.0f;
}

// ---------------- launch ----------------
extern "C" void kernel_launch(void* const* d_in, const int* in_sizes, int n_in,
                              void* d_out, int out_size) {
    const float* x  = (const float*)d_in[0];
    const int*   ei = (const int*)d_in[1];   // int32 (JAX default x64-disabled)
    // d_in[2] = edge_index_global (unused by reference outputs)
    const float* W1 = (const float*)d_in[3];
    const float* b1 = (const float*)d_in[4];
    const float* W2 = (const float*)d_in[5];
    const float* b2 = (const float*)d_in[6];

    float* out   = (float*)d_out;
    float* probs = out;                  // [EDGES]
    float* acts  = out + EDGES;          // [EDGES]
    float* P     = out + 2 * EDGES;      // [NODES*NODES]

    prep_kernel<<<NODES, FDIM>>>(x, W1, b1);
    edge_kernel<<<EDGES / 256, 256>>>(x, ei, W1, W2, b2, probs, acts);
    dim3 grid(NODES / BI, NODES / BJ);
    dense_kernel<<<grid, 256>>>(x, W1, W2, b2, P);
}

// round 9
// speedup vs baseline: 2.1396x; 2.1396x over previous
#include <cuda_runtime.h>
#include <math.h>
#include <stdint.h>

#define NODES 1024
#define FDIM  64
#define HID   32
#define HH    16
#define EDGES 65536
#define BI    32     // i-rows per dense CTA
#define BJ    128    // j-cols per dense CTA (8 warps x 16)

// Precomputed per-node terms: A = x @ W1[0:64] + b1 ; B = x @ W1[64:128]
__device__ float g_A[NODES * HID];
__device__ float g_B[NODES * HID];

__device__ __forceinline__ float sigmoid_f(float v) {
    return 1.0f / (1.0f + expf(-v));
}

// ======================= prep: per-node A/B =======================
__global__ void prep_kernel(const float* __restrict__ x,
                            const float* __restrict__ W1,
                            const float* __restrict__ b1) {
    __shared__ float xr[4][FDIM];
    int t = threadIdx.x;                     // 256
    int nl = t >> 6, s = t & 63;
    int node = blockIdx.x * 4 + nl;
    xr[nl][s] = x[node * FDIM + s];
    __syncthreads();
    int h = s & 31;
    const float* W = W1 + ((s < 32) ? 0 : FDIM * HID);
    float acc = (s < 32) ? b1[h] : 0.0f;
#pragma unroll
    for (int f = 0; f < FDIM; f++)
        acc = fmaf(xr[nl][f], W[f * HID + h], acc);
    if (s < 32) g_A[node * HID + h] = acc;
    else        g_B[node * HID + h] = acc;
}

// ======================= dense all-pairs: mma.sync tf32 =======================
// smem (floats): sW [16][32][8] = 4096 | sXI [32][64] = 2048 | sXJ [128][64] = 8192 | sA [32][32] = 1024
#define SW_OFF  0
#define SXI_OFF 4096
#define SXJ_OFF (4096 + 2048)
#define SA_OFF  (4096 + 2048 + 8192)
#define DENSE_SMEM_F (4096 + 2048 + 8192 + 1024)

__device__ __forceinline__ uint32_t cvt_tf32(float v) {
    uint32_t u;
    asm("cvt.rna.tf32.f32 %0, %1;" : "=r"(u) : "f"(v));
    return u;
}

__device__ __forceinline__ void mma_tf32(float* D, uint32_t a0, uint32_t a1,
                                         uint32_t a2, uint32_t a3,
                                         uint32_t b0, uint32_t b1) {
    asm volatile(
        "mma.sync.aligned.m16n8k8.row.col.f32.tf32.tf32.f32 "
        "{%0,%1,%2,%3}, {%4,%5,%6,%7}, {%8,%9}, {%0,%1,%2,%3};"
        : "+f"(D[0]), "+f"(D[1]), "+f"(D[2]), "+f"(D[3])
        : "r"(a0), "r"(a1), "r"(a2), "r"(a3), "r"(b0), "r"(b1));
}

__global__ __launch_bounds__(256, 2)
void dense_mma_kernel(const float* __restrict__ x,
                      const float* __restrict__ W1,
                      const float* __restrict__ W2,
                      const float* __restrict__ b2,
                      float* __restrict__ P) {
    extern __shared__ float sm[];
    float* sW  = sm + SW_OFF;
    float* sXI = sm + SXI_OFF;
    float* sXJ = sm + SXJ_OFF;
    float* sA  = sm + SA_OFF;

    int t  = threadIdx.x;
    int i0 = blockIdx.x * BI;
    int j0 = blockIdx.y * BJ;

    // ---- stage xj block (row-major) ----
    for (int k = t; k < BJ * (FDIM / 4); k += 256) {
        int row = k >> 4, c4 = k & 15;
        float4 v = __ldg((const float4*)(x + (j0 + row) * FDIM) + c4);
        ((float4*)(sXJ + row * FDIM))[c4] = v;
    }
    // ---- stage xi block, transposed to [i][q*16 + m] where f = 4m+q ----
    for (int k = t; k < BI * (FDIM / 4); k += 256) {
        int row = k >> 4, c4 = k & 15;
        float4 v = __ldg((const float4*)(x + (i0 + row) * FDIM) + c4);
        float vv[4] = {v.x, v.y, v.z, v.w};
#pragma unroll
        for (int u = 0; u < 4; u++) {
            int f = c4 * 4 + u;
            sXI[row * FDIM + (f & 3) * 16 + (f >> 2)] = vv[u];
        }
    }
    // ---- stage A_i ----
    for (int k = t; k < BI * HID; k += 256)
        sA[k] = g_A[(i0 + (k >> 5)) * HID + (k & 31)];
    // ---- prepack B fragments (W1 rows 128..255, tf32) ----
    for (int g = t; g < 512; g += 256) {
        int s = g >> 5, ln = g & 31;
        int qq = ln & 3, rr = ln >> 2;
        float* dst = sW + (s * 32 + ln) * 8;
#pragma unroll
        for (int nt = 0; nt < 4; nt++) {
            float w0 = W1[(128 + 8 * s + qq) * HID + nt * 8 + rr];
            float w1 = W1[(128 + 8 * s + 4 + qq) * HID + nt * 8 + rr];
            dst[nt]     = __uint_as_float(cvt_tf32(w0));
            dst[4 + nt] = __uint_as_float(cvt_tf32(w1));
        }
    }
    __syncthreads();

    int lane = t & 31, wid = t >> 5;
    int q = lane & 3, r = lane >> 2;
    int jr0 = wid * 16 + r;        // local j row of D rows [0..7]
    int jr1 = jr0 + 8;             // local j row of D rows [8..15]

    // register cache: xj slices (feats f = 4m+q), reused across all i
    float xj0[16], xj1[16];
#pragma unroll
    for (int m = 0; m < 16; m++) {
        xj0[m] = sXJ[jr0 * FDIM + 4 * m + q];
        xj1[m] = sXJ[jr1 * FDIM + 4 * m + q];
    }
    // epilogue constants: B_j and W2 at this thread's hid columns
    float bj0[8], bj1[8], w2l[8];
#pragma unroll
    for (int nt = 0; nt < 4; nt++) {
        int h = nt * 8 + 2 * q;
        bj0[2 * nt]     = g_B[(j0 + jr0) * HID + h];
        bj0[2 * nt + 1] = g_B[(j0 + jr0) * HID + h + 1];
        bj1[2 * nt]     = g_B[(j0 + jr1) * HID + h];
        bj1[2 * nt + 1] = g_B[(j0 + jr1) * HID + h + 1];
        w2l[2 * nt]     = __ldg(W2 + h);
        w2l[2 * nt + 1] = __ldg(W2 + h + 1);
    }
    float b2v = __ldg(b2);

    for (int ii = 0; ii < BI; ii++) {
        float D[16];
#pragma unroll
        for (int z = 0; z < 16; z++) D[z] = 0.0f;

#pragma unroll
        for (int s = 0; s < 16; s++) {
            int m = 2 * (s & 7);
            float2 xiv = *(const float2*)(sXI + ii * FDIM + q * 16 + m);
            float a0, a1, a2, a3;
            if (s < 8) {             // |xi - xj| block (W1 rows 128..191)
                a0 = fabsf(xiv.x - xj0[m]);
                a1 = fabsf(xiv.x - xj1[m]);
                a2 = fabsf(xiv.y - xj0[m + 1]);
                a3 = fabsf(xiv.y - xj1[m + 1]);
            } else {                 // xi * xj block (W1 rows 192..255)
                a0 = xiv.x * xj0[m];
                a1 = xiv.x * xj1[m];
                a2 = xiv.y * xj0[m + 1];
                a3 = xiv.y * xj1[m + 1];
            }
            uint32_t ua0 = cvt_tf32(a0), ua1 = cvt_tf32(a1);
            uint32_t ua2 = cvt_tf32(a2), ua3 = cvt_tf32(a3);

            const float* bp = sW + (s * 32 + lane) * 8;
            float4 bv0 = *(const float4*)bp;        // b0 for nt=0..3
            float4 bv1 = *(const float4*)(bp + 4);  // b1 for nt=0..3

            mma_tf32(D + 0,  ua0, ua1, ua2, ua3, __float_as_uint(bv0.x), __float_as_uint(bv1.x));
            mma_tf32(D + 4,  ua0, ua1, ua2, ua3, __float_as_uint(bv0.y), __float_as_uint(bv1.y));
            mma_tf32(D + 8,  ua0, ua1, ua2, ua3, __float_as_uint(bv0.z), __float_as_uint(bv1.z));
            mma_tf32(D + 12, ua0, ua1, ua2, ua3, __float_as_uint(bv0.w), __float_as_uint(bv1.w));
        }

        // ---- epilogue: add per-node terms, ReLU, W2 dot, quad reduce ----
        float p0 = 0.0f, p1 = 0.0f;
#pragma unroll
        for (int nt = 0; nt < 4; nt++) {
            float2 aiv = *(const float2*)(sA + ii * HID + nt * 8 + 2 * q);
            p0 += fmaxf(D[nt * 4 + 0] + aiv.x + bj0[2 * nt],     0.0f) * w2l[2 * nt];
            p0 += fmaxf(D[nt * 4 + 1] + aiv.y + bj0[2 * nt + 1], 0.0f) * w2l[2 * nt + 1];
            p1 += fmaxf(D[nt * 4 + 2] + aiv.x + bj1[2 * nt],     0.0f) * w2l[2 * nt];
            p1 += fmaxf(D[nt * 4 + 3] + aiv.y + bj1[2 * nt + 1], 0.0f) * w2l[2 * nt + 1];
        }
        p0 += __shfl_xor_sync(0xFFFFFFFF, p0, 1);
        p0 += __shfl_xor_sync(0xFFFFFFFF, p0, 2);
        p1 += __shfl_xor_sync(0xFFFFFFFF, p1, 1);
        p1 += __shfl_xor_sync(0xFFFFFFFF, p1, 2);
        if (q == 0) {
            P[(i0 + ii) * NODES + j0 + jr0] = sigmoid_f(p0 + b2v);
            P[(i0 + ii) * NODES + j0 + jr1] = sigmoid_f(p1 + b2v);
        }
    }
}

// ======================= sparse edge branch (fp32, exact) =======================
__device__ __forceinline__ unsigned long long pack2(float lo, float hi) {
    unsigned long long r;
    asm("mov.b64 %0, {%1, %2};" : "=l"(r) : "f"(lo), "f"(hi));
    return r;
}
__device__ __forceinline__ void unpack2(unsigned long long v, float& lo, float& hi) {
    asm("mov.b64 {%0, %1}, %2;" : "=f"(lo), "=f"(hi) : "l"(v));
}
__device__ __forceinline__ unsigned long long ffma2(unsigned long long a,
                                                    unsigned long long b,
                                                    unsigned long long c) {
    unsigned long long d;
    asm("fma.rn.f32x2 %0, %1, %2, %3;" : "=l"(d) : "l"(a), "l"(b), "l"(c));
    return d;
}

__global__ __launch_bounds__(256)
void edge_kernel(const float* __restrict__ x,
                 const int* __restrict__ ei,   // int32 (JAX x64 disabled)
                 const float* __restrict__ W1,
                 const float* __restrict__ W2,
                 const float* __restrict__ b2,
                 float* __restrict__ probs,
                 float* __restrict__ acts) {
    __shared__ unsigned long long s_Wc[FDIM][HH];
    __shared__ unsigned long long s_Wd[FDIM][HH];
    __shared__ float s_W2[HID];
    int t = threadIdx.x;
    for (int k = t; k < FDIM * HH; k += 256) {
        int f = k >> 4, hh = k & 15;
        float2 c = ((const float2*)(W1 + (128 + f) * HID))[hh];
        float2 d = ((const float2*)(W1 + (192 + f) * HID))[hh];
        s_Wc[f][hh] = pack2(c.x, c.y);
        s_Wd[f][hh] = pack2(d.x, d.y);
    }
    if (t < HID) s_W2[t] = W2[t];
    __syncthreads();

    int e = blockIdx.x * 256 + t;
    int s = ei[e];
    int d = ei[EDGES + e];

    unsigned long long acc[HH];
    {
        const float* Ar = g_A + s * HID;
        const float* Br = g_B + d * HID;
#pragma unroll
        for (int hh = 0; hh < HH; hh++)
            acc[hh] = pack2(Ar[2 * hh] + Br[2 * hh], Ar[2 * hh + 1] + Br[2 * hh + 1]);
    }

    const float4* xs4 = (const float4*)(x + s * FDIM);
    const float4* xd4 = (const float4*)(x + d * FDIM);
#pragma unroll 4
    for (int c = 0; c < FDIM / 4; c++) {
        float4 a = __ldg(xs4 + c);
        float4 b = __ldg(xd4 + c);
        float av[4] = {a.x, a.y, a.z, a.w};
        float bv[4] = {b.x, b.y, b.z, b.w};
#pragma unroll
        for (int u = 0; u < 4; u++) {
            int f = c * 4 + u;
            float ad = fabsf(av[u] - bv[u]);
            float pr = av[u] * bv[u];
            unsigned long long dd = pack2(ad, ad);
            unsigned long long pm = pack2(pr, pr);
#pragma unroll
            for (int hh = 0; hh < HH; hh++) {
                acc[hh] = ffma2(dd, s_Wc[f][hh], acc[hh]);
                acc[hh] = ffma2(pm, s_Wd[f][hh], acc[hh]);
            }
        }
    }

    float logit = b2[0];
#pragma unroll
    for (int hh = 0; hh < HH; hh++) {
        float lo, hi;
        unpack2(acc[hh], lo, hi);
        logit += fmaxf(lo, 0.0f) * s_W2[2 * hh] + fmaxf(hi, 0.0f) * s_W2[2 * hh + 1];
    }
    float prob = 1.0f / (1.0f + expf(-logit));
    probs[e] = prob;
    acts[e]  = (prob > 0.4f) ? 1.0f : 0.0f;
}

// ======================= launch =======================
extern "C" void kernel_launch(void* const* d_in, const int* in_sizes, int n_in,
                              void* d_out, int out_size) {
    const float* x  = (const float*)d_in[0];
    const int*   ei = (const int*)d_in[1];     // int32 (JAX x64 disabled)
    const float* W1 = (const float*)d_in[3];
    const float* b1 = (const float*)d_in[4];
    const float* W2 = (const float*)d_in[5];
    const float* b2 = (const float*)d_in[6];

    float* out   = (float*)d_out;
    float* probs = out;
    float* acts  = out + EDGES;
    float* P     = out + 2 * EDGES;

    static int smem_set = 0;
    if (!smem_set) {
        cudaFuncSetAttribute(dense_mma_kernel,
                             cudaFuncAttributeMaxDynamicSharedMemorySize,
                             DENSE_SMEM_F * 4);
        smem_set = 1;
    }

    prep_kernel<<<NODES / 4, 256>>>(x, W1, b1);
    edge_kernel<<<EDGES / 256, 256>>>(x, ei, W1, W2, b2, probs, acts);
    dim3 grid(NODES / BI, NODES / BJ);
    dense_mma_kernel<<<grid, 256, DENSE_SMEM_F * 4>>>(x, W1, W2, b2, P);
}

// round 10
// speedup vs baseline: 2.3504x; 1.0985x over previous
#include <cuda_runtime.h>
#include <math.h>
#include <stdint.h>

#define NODES 1024
#define FDIM  64
#define HID   32
#define HH    16
#define EDGES 65536
#define BI    32     // i-rows per dense CTA
#define BJ    128    // j-cols per dense CTA (8 warps x 16)

// Precomputed per-node terms: A = x @ W1[0:64] + b1 ; B = x @ W1[64:128]
__device__ float g_A[NODES * HID];
__device__ float g_B[NODES * HID];

__device__ __forceinline__ float sigmoid_f(float v) {
    return 1.0f / (1.0f + expf(-v));
}

// ======================= prep: per-node A/B =======================
__global__ void prep_kernel(const float* __restrict__ x,
                            const float* __restrict__ W1,
                            const float* __restrict__ b1) {
    __shared__ float xr[4][FDIM];
    int t = threadIdx.x;                     // 256
    int nl = t >> 6, s = t & 63;
    int node = blockIdx.x * 4 + nl;
    xr[nl][s] = x[node * FDIM + s];
    __syncthreads();
    int h = s & 31;
    const float* W = W1 + ((s < 32) ? 0 : FDIM * HID);
    float acc = (s < 32) ? b1[h] : 0.0f;
#pragma unroll
    for (int f = 0; f < FDIM; f++)
        acc = fmaf(xr[nl][f], W[f * HID + h], acc);
    if (s < 32) g_A[node * HID + h] = acc;
    else        g_B[node * HID + h] = acc;
}

// ======================= dense all-pairs: mma.sync tf32 =======================
// smem (floats): sW [16][32][8] = 4096 | sXI [32][64] = 2048 | sXJ [128][64] = 8192 | sA [32][32] = 1024
#define SW_OFF  0
#define SXI_OFF 4096
#define SXJ_OFF (4096 + 2048)
#define SA_OFF  (4096 + 2048 + 8192)
#define DENSE_SMEM_F (4096 + 2048 + 8192 + 1024)

__device__ __forceinline__ uint32_t cvt_tf32(float v) {
    uint32_t u;
    asm("cvt.rna.tf32.f32 %0, %1;" : "=r"(u) : "f"(v));
    return u;
}

__device__ __forceinline__ void mma_tf32(float* D, uint32_t a0, uint32_t a1,
                                         uint32_t a2, uint32_t a3,
                                         uint32_t b0, uint32_t b1) {
    asm volatile(
        "mma.sync.aligned.m16n8k8.row.col.f32.tf32.tf32.f32 "
        "{%0,%1,%2,%3}, {%4,%5,%6,%7}, {%8,%9}, {%0,%1,%2,%3};"
        : "+f"(D[0]), "+f"(D[1]), "+f"(D[2]), "+f"(D[3])
        : "r"(a0), "r"(a1), "r"(a2), "r"(a3), "r"(b0), "r"(b1));
}

__global__ __launch_bounds__(256, 1)
void dense_mma_kernel(const float* __restrict__ x,
                      const float* __restrict__ W1,
                      const float* __restrict__ W2,
                      const float* __restrict__ b2,
                      float* __restrict__ P) {
    extern __shared__ float sm[];
    float* sW  = sm + SW_OFF;
    float* sXI = sm + SXI_OFF;
    float* sXJ = sm + SXJ_OFF;
    float* sA  = sm + SA_OFF;

    int t  = threadIdx.x;
    int i0 = blockIdx.x * BI;
    int j0 = blockIdx.y * BJ;

    // ---- stage xj block (row-major) ----
    for (int k = t; k < BJ * (FDIM / 4); k += 256) {
        int row = k >> 4, c4 = k & 15;
        float4 v = __ldg((const float4*)(x + (j0 + row) * FDIM) + c4);
        ((float4*)(sXJ + row * FDIM))[c4] = v;
    }
    // ---- stage xi block, transposed to [i][q*16 + m] where f = 4m+q ----
    for (int k = t; k < BI * (FDIM / 4); k += 256) {
        int row = k >> 4, c4 = k & 15;
        float4 v = __ldg((const float4*)(x + (i0 + row) * FDIM) + c4);
        float vv[4] = {v.x, v.y, v.z, v.w};
#pragma unroll
        for (int u = 0; u < 4; u++) {
            int f = c4 * 4 + u;
            sXI[row * FDIM + (f & 3) * 16 + (f >> 2)] = vv[u];
        }
    }
    // ---- stage A_i ----
    for (int k = t; k < BI * HID; k += 256)
        sA[k] = g_A[(i0 + (k >> 5)) * HID + (k & 31)];
    // ---- prepack B fragments (W1 rows 128..255, tf32) ----
    for (int g = t; g < 512; g += 256) {
        int s = g >> 5, ln = g & 31;
        int qq = ln & 3, rr = ln >> 2;
        float* dst = sW + (s * 32 + ln) * 8;
#pragma unroll
        for (int nt = 0; nt < 4; nt++) {
            float w0 = W1[(128 + 8 * s + qq) * HID + nt * 8 + rr];
            float w1 = W1[(128 + 8 * s + 4 + qq) * HID + nt * 8 + rr];
            dst[nt]     = __uint_as_float(cvt_tf32(w0));
            dst[4 + nt] = __uint_as_float(cvt_tf32(w1));
        }
    }
    __syncthreads();

    int lane = t & 31, wid = t >> 5;
    int q = lane & 3, r = lane >> 2;
    int jr0 = wid * 16 + r;        // local j row of D rows [0..7]
    int jr1 = jr0 + 8;             // local j row of D rows [8..15]

    // ---- hoist ALL B fragments into registers (loop-invariant weights) ----
    float4 bw0[16], bw1[16];
#pragma unroll
    for (int s = 0; s < 16; s++) {
        const float* bp = sW + (s * 32 + lane) * 8;
        bw0[s] = *(const float4*)bp;
        bw1[s] = *(const float4*)(bp + 4);
    }

    // register cache: xj slices (feats f = 4m+q), reused across all i
    float xj0[16], xj1[16];
#pragma unroll
    for (int m = 0; m < 16; m++) {
        xj0[m] = sXJ[jr0 * FDIM + 4 * m + q];
        xj1[m] = sXJ[jr1 * FDIM + 4 * m + q];
    }
    // epilogue constants: B_j and W2 at this thread's hid columns
    float bj0[8], bj1[8], w2l[8];
#pragma unroll
    for (int nt = 0; nt < 4; nt++) {
        int h = nt * 8 + 2 * q;
        bj0[2 * nt]     = g_B[(j0 + jr0) * HID + h];
        bj0[2 * nt + 1] = g_B[(j0 + jr0) * HID + h + 1];
        bj1[2 * nt]     = g_B[(j0 + jr1) * HID + h];
        bj1[2 * nt + 1] = g_B[(j0 + jr1) * HID + h + 1];
        w2l[2 * nt]     = __ldg(W2 + h);
        w2l[2 * nt + 1] = __ldg(W2 + h + 1);
    }
    float b2v = __ldg(b2);

    for (int ii = 0; ii < BI; ii++) {
        float D[16];
#pragma unroll
        for (int z = 0; z < 16; z++) D[z] = 0.0f;

#pragma unroll
        for (int s = 0; s < 16; s++) {
            int m = 2 * (s & 7);
            float2 xiv = *(const float2*)(sXI + ii * FDIM + q * 16 + m);
            float a0, a1, a2, a3;
            if (s < 8) {             // |xi - xj| block (W1 rows 128..191)
                a0 = fabsf(xiv.x - xj0[m]);
                a1 = fabsf(xiv.x - xj1[m]);
                a2 = fabsf(xiv.y - xj0[m + 1]);
                a3 = fabsf(xiv.y - xj1[m + 1]);
            } else {                 // xi * xj block (W1 rows 192..255)
                a0 = xiv.x * xj0[m];
                a1 = xiv.x * xj1[m];
                a2 = xiv.y * xj0[m + 1];
                a3 = xiv.y * xj1[m + 1];
            }
            uint32_t ua0 = cvt_tf32(a0), ua1 = cvt_tf32(a1);
            uint32_t ua2 = cvt_tf32(a2), ua3 = cvt_tf32(a3);

            mma_tf32(D + 0,  ua0, ua1, ua2, ua3,
                     __float_as_uint(bw0[s].x), __float_as_uint(bw1[s].x));
            mma_tf32(D + 4,  ua0, ua1, ua2, ua3,
                     __float_as_uint(bw0[s].y), __float_as_uint(bw1[s].y));
            mma_tf32(D + 8,  ua0, ua1, ua2, ua3,
                     __float_as_uint(bw0[s].z), __float_as_uint(bw1[s].z));
            mma_tf32(D + 12, ua0, ua1, ua2, ua3,
                     __float_as_uint(bw0[s].w), __float_as_uint(bw1[s].w));
        }

        // ---- epilogue: add per-node terms, ReLU, W2 dot, quad reduce ----
        float p0 = 0.0f, p1 = 0.0f;
#pragma unroll
        for (int nt = 0; nt < 4; nt++) {
            float2 aiv = *(const float2*)(sA + ii * HID + nt * 8 + 2 * q);
            p0 += fmaxf(D[nt * 4 + 0] + aiv.x + bj0[2 * nt],     0.0f) * w2l[2 * nt];
            p0 += fmaxf(D[nt * 4 + 1] + aiv.y + bj0[2 * nt + 1], 0.0f) * w2l[2 * nt + 1];
            p1 += fmaxf(D[nt * 4 + 2] + aiv.x + bj1[2 * nt],     0.0f) * w2l[2 * nt];
            p1 += fmaxf(D[nt * 4 + 3] + aiv.y + bj1[2 * nt + 1], 0.0f) * w2l[2 * nt + 1];
        }
        p0 += __shfl_xor_sync(0xFFFFFFFF, p0, 1);
        p0 += __shfl_xor_sync(0xFFFFFFFF, p0, 2);
        p1 += __shfl_xor_sync(0xFFFFFFFF, p1, 1);
        p1 += __shfl_xor_sync(0xFFFFFFFF, p1, 2);
        if (q == 0) {
            P[(i0 + ii) * NODES + j0 + jr0] = sigmoid_f(p0 + b2v);
            P[(i0 + ii) * NODES + j0 + jr1] = sigmoid_f(p1 + b2v);
        }
    }
}

// ======================= sparse edge branch (fp32, exact) =======================
__device__ __forceinline__ unsigned long long pack2(float lo, float hi) {
    unsigned long long r;
    asm("mov.b64 %0, {%1, %2};" : "=l"(r) : "f"(lo), "f"(hi));
    return r;
}
__device__ __forceinline__ void unpack2(unsigned long long v, float& lo, float& hi) {
    asm("mov.b64 {%0, %1}, %2;" : "=f"(lo), "=f"(hi) : "l"(v));
}
__device__ __forceinline__ unsigned long long ffma2(unsigned long long a,
                                                    unsigned long long b,
                                                    unsigned long long c) {
    unsigned long long d;
    asm("fma.rn.f32x2 %0, %1, %2, %3;" : "=l"(d) : "l"(a), "l"(b), "l"(c));
    return d;
}

__global__ __launch_bounds__(256)
void edge_kernel(const float* __restrict__ x,
                 const int* __restrict__ ei,   // int32 (JAX x64 disabled)
                 const float* __restrict__ W1,
                 const float* __restrict__ W2,
                 const float* __restrict__ b2,
                 float* __restrict__ probs,
                 float* __restrict__ acts) {
    __shared__ unsigned long long s_Wc[FDIM][HH];
    __shared__ unsigned long long s_Wd[FDIM][HH];
    __shared__ float s_W2[HID];
    int t = threadIdx.x;
    for (int k = t; k < FDIM * HH; k += 256) {
        int f = k >> 4, hh = k & 15;
        float2 c = ((const float2*)(W1 + (128 + f) * HID))[hh];
        float2 d = ((const float2*)(W1 + (192 + f) * HID))[hh];
        s_Wc[f][hh] = pack2(c.x, c.y);
        s_Wd[f][hh] = pack2(d.x, d.y);
    }
    if (t < HID) s_W2[t] = W2[t];
    __syncthreads();

    int e = blockIdx.x * 256 + t;
    int s = ei[e];
    int d = ei[EDGES + e];

    unsigned long long acc[HH];
    {
        const float* Ar = g_A + s * HID;
        const float* Br = g_B + d * HID;
#pragma unroll
        for (int hh = 0; hh < HH; hh++)
            acc[hh] = pack2(Ar[2 * hh] + Br[2 * hh], Ar[2 * hh + 1] + Br[2 * hh + 1]);
    }

    const float4* xs4 = (const float4*)(x + s * FDIM);
    const float4* xd4 = (const float4*)(x + d * FDIM);
#pragma unroll 4
    for (int c = 0; c < FDIM / 4; c++) {
        float4 a = __ldg(xs4 + c);
        float4 b = __ldg(xd4 + c);
        float av[4] = {a.x, a.y, a.z, a.w};
        float bv[4] = {b.x, b.y, b.z, b.w};
#pragma unroll
        for (int u = 0; u < 4; u++) {
            int f = c * 4 + u;
            float ad = fabsf(av[u] - bv[u]);
            float pr = av[u] * bv[u];
            unsigned long long dd = pack2(ad, ad);
            unsigned long long pm = pack2(pr, pr);
#pragma unroll
            for (int hh = 0; hh < HH; hh++) {
                acc[hh] = ffma2(dd, s_Wc[f][hh], acc[hh]);
                acc[hh] = ffma2(pm, s_Wd[f][hh], acc[hh]);
            }
        }
    }

    float logit = b2[0];
#pragma unroll
    for (int hh = 0; hh < HH; hh++) {
        float lo, hi;
        unpack2(acc[hh], lo, hi);
        logit += fmaxf(lo, 0.0f) * s_W2[2 * hh] + fmaxf(hi, 0.0f) * s_W2[2 * hh + 1];
    }
    float prob = 1.0f / (1.0f + expf(-logit));
    probs[e] = prob;
    acts[e]  = (prob > 0.4f) ? 1.0f : 0.0f;
}

// ======================= launch =======================
extern "C" void kernel_launch(void* const* d_in, const int* in_sizes, int n_in,
                              void* d_out, int out_size) {
    const float* x  = (const float*)d_in[0];
    const int*   ei = (const int*)d_in[1];     // int32 (JAX x64 disabled)
    const float* W1 = (const float*)d_in[3];
    const float* b1 = (const float*)d_in[4];
    const float* W2 = (const float*)d_in[5];
    const float* b2 = (const float*)d_in[6];

    float* out   = (float*)d_out;
    float* probs = out;
    float* acts  = out + EDGES;
    float* P     = out + 2 * EDGES;

    static int smem_set = 0;
    if (!smem_set) {
        cudaFuncSetAttribute(dense_mma_kernel,
                             cudaFuncAttributeMaxDynamicSharedMemorySize,
                             DENSE_SMEM_F * 4);
        smem_set = 1;
    }

    prep_kernel<<<NODES / 4, 256>>>(x, W1, b1);
    edge_kernel<<<EDGES / 256, 256>>>(x, ei, W1, W2, b2, probs, acts);
    dim3 grid(NODES / BI, NODES / BJ);
    dense_mma_kernel<<<grid, 256, DENSE_SMEM_F * 4>>>(x, W1, W2, b2, P);
}

// round 11
// speedup vs baseline: 2.8769x; 1.2240x over previous
#include <cuda_runtime.h>
#include <math.h>
#include <stdint.h>

#define NODES 1024
#define FDIM  64
#define HID   32
#define HH    16
#define EDGES 65536
#define BI    32     // i-rows per dense CTA
#define BJ    128    // j-cols per dense CTA (8 warps x 16)

// Precomputed per-node terms: A = x @ W1[0:64] + b1 ; B = x @ W1[64:128]
__device__ float g_A[NODES * HID];
__device__ float g_B[NODES * HID];

__device__ __forceinline__ float sigmoid_f(float v) {
    return 1.0f / (1.0f + expf(-v));
}

// ======================= prep: per-node A/B =======================
__global__ void prep_kernel(const float* __restrict__ x,
                            const float* __restrict__ W1,
                            const float* __restrict__ b1) {
    __shared__ float xr[4][FDIM];
    int t = threadIdx.x;                     // 256
    int nl = t >> 6, s = t & 63;
    int node = blockIdx.x * 4 + nl;
    xr[nl][s] = x[node * FDIM + s];
    __syncthreads();
    int h = s & 31;
    const float* W = W1 + ((s < 32) ? 0 : FDIM * HID);
    float acc = (s < 32) ? b1[h] : 0.0f;
#pragma unroll
    for (int f = 0; f < FDIM; f++)
        acc = fmaf(xr[nl][f], W[f * HID + h], acc);
    if (s < 32) g_A[node * HID + h] = acc;
    else        g_B[node * HID + h] = acc;
}

// ======================= dense all-pairs: mma.sync fp16 m16n8k16 =======================
// smem (floats): sW [8][32][8] u32 = 2048 | sXI [32][64] = 2048 | sXJ [128][64] = 8192 | sA [32][32] = 1024
#define SW_OFF  0
#define SXI_OFF 2048
#define SXJ_OFF (2048 + 2048)
#define SA_OFF  (2048 + 2048 + 8192)
#define DENSE_SMEM_F (2048 + 2048 + 8192 + 1024)

// pack two f32 -> f16x2 (lo in lower half)
__device__ __forceinline__ uint32_t pack_h2(float lo, float hi) {
    uint32_t r;
    asm("cvt.rn.f16x2.f32 %0, %1, %2;" : "=r"(r) : "f"(hi), "f"(lo));
    return r;
}

__device__ __forceinline__ void mma_f16(float* D, uint32_t a0, uint32_t a1,
                                        uint32_t a2, uint32_t a3,
                                        uint32_t b0, uint32_t b1) {
    asm volatile(
        "mma.sync.aligned.m16n8k16.row.col.f32.f16.f16.f32 "
        "{%0,%1,%2,%3}, {%4,%5,%6,%7}, {%8,%9}, {%0,%1,%2,%3};"
        : "+f"(D[0]), "+f"(D[1]), "+f"(D[2]), "+f"(D[3])
        : "r"(a0), "r"(a1), "r"(a2), "r"(a3), "r"(b0), "r"(b1));
}

__global__ __launch_bounds__(256, 1)
void dense_mma_kernel(const float* __restrict__ x,
                      const float* __restrict__ W1,
                      const float* __restrict__ W2,
                      const float* __restrict__ b2,
                      float* __restrict__ P) {
    extern __shared__ float sm[];
    uint32_t* sW = (uint32_t*)(sm + SW_OFF);   // [8 steps][32 lanes][8 u32]
    float* sXI = sm + SXI_OFF;                 // [32][64] row-major
    float* sXJ = sm + SXJ_OFF;                 // [128][64] row-major
    float* sA  = sm + SA_OFF;                  // [32][32]

    int t  = threadIdx.x;
    int i0 = blockIdx.x * BI;
    int j0 = blockIdx.y * BJ;

    // ---- stage xj block ----
    for (int k = t; k < BJ * (FDIM / 4); k += 256) {
        int row = k >> 4, c4 = k & 15;
        float4 v = __ldg((const float4*)(x + (j0 + row) * FDIM) + c4);
        ((float4*)(sXJ + row * FDIM))[c4] = v;
    }
    // ---- stage xi block (plain row-major) ----
    for (int k = t; k < BI * (FDIM / 4); k += 256) {
        int row = k >> 4, c4 = k & 15;
        float4 v = __ldg((const float4*)(x + (i0 + row) * FDIM) + c4);
        ((float4*)(sXI + row * FDIM))[c4] = v;
    }
    // ---- stage A_i ----
    for (int k = t; k < BI * HID; k += 256)
        sA[k] = g_A[(i0 + (k >> 5)) * HID + (k & 31)];
    // ---- prepack B fragments (W1 rows 128..255 -> f16x2, per-lane layout) ----
    // step s (0..7): k-block = s*16. k<64 -> diff rows (128+f), else prod rows (192+f-64? no: 128+64+f)
    for (int g = t; g < 256; g += 256) { }
    for (int g = t; g < 8 * 32; g += 256) {
        int s = g >> 5, ln = g & 31;
        int qq = ln & 3, rr = ln >> 2;
        uint32_t* dst = sW + (s * 32 + ln) * 8;
        int kb = s * 16;
#pragma unroll
        for (int nt = 0; nt < 4; nt++) {
            int n = nt * 8 + rr;
            int f0 = kb + 2 * qq;        // global k for b0 pair
            int f2 = kb + 2 * qq + 8;    // global k for b1 pair
            // feature K maps to W1 row 128+K (diff block then prod block contiguous)
            float w00 = W1[(128 + f0) * HID + n];
            float w01 = W1[(128 + f0 + 1) * HID + n];
            float w20 = W1[(128 + f2) * HID + n];
            float w21 = W1[(128 + f2 + 1) * HID + n];
            dst[nt]     = pack_h2(w00, w01);
            dst[4 + nt] = pack_h2(w20, w21);
        }
    }
    __syncthreads();

    int lane = t & 31, wid = t >> 5;
    int q = lane & 3, r = lane >> 2;
    int jr0 = wid * 16 + r;        // D rows 0..7  -> j index
    int jr1 = jr0 + 8;             // D rows 8..15 -> j index

    // ---- hoist all B fragments to registers: 8 steps x 8 u32 = 64 regs ----
    uint32_t bf[8][8];
#pragma unroll
    for (int s = 0; s < 8; s++) {
        const uint32_t* bp = sW + (s * 32 + lane) * 8;
        float4 v0 = *(const float4*)bp;
        float4 v1 = *(const float4*)(bp + 4);
        bf[s][0] = __float_as_uint(v0.x); bf[s][1] = __float_as_uint(v0.y);
        bf[s][2] = __float_as_uint(v0.z); bf[s][3] = __float_as_uint(v0.w);
        bf[s][4] = __float_as_uint(v1.x); bf[s][5] = __float_as_uint(v1.y);
        bf[s][6] = __float_as_uint(v1.z); bf[s][7] = __float_as_uint(v1.w);
    }

    // ---- xj register cache: feats u*16 + {2q,2q+1} and {2q+8,2q+9}, rows jr0/jr1 ----
    float2 xjA0[4], xjB0[4], xjA1[4], xjB1[4];
#pragma unroll
    for (int u = 0; u < 4; u++) {
        xjA0[u] = *(const float2*)(sXJ + jr0 * FDIM + u * 16 + 2 * q);
        xjB0[u] = *(const float2*)(sXJ + jr0 * FDIM + u * 16 + 2 * q + 8);
        xjA1[u] = *(const float2*)(sXJ + jr1 * FDIM + u * 16 + 2 * q);
        xjB1[u] = *(const float2*)(sXJ + jr1 * FDIM + u * 16 + 2 * q + 8);
    }

    // epilogue constants
    float bj0[8], bj1[8], w2l[8];
#pragma unroll
    for (int nt = 0; nt < 4; nt++) {
        int h = nt * 8 + 2 * q;
        bj0[2 * nt]     = g_B[(j0 + jr0) * HID + h];
        bj0[2 * nt + 1] = g_B[(j0 + jr0) * HID + h + 1];
        bj1[2 * nt]     = g_B[(j0 + jr1) * HID + h];
        bj1[2 * nt + 1] = g_B[(j0 + jr1) * HID + h + 1];
        w2l[2 * nt]     = __ldg(W2 + h);
        w2l[2 * nt + 1] = __ldg(W2 + h + 1);
    }
    float b2v = __ldg(b2);

    for (int ii = 0; ii < BI; ii++) {
        // per-i xi cache (same feats as xj cache)
        float2 xiA[4], xiB[4];
#pragma unroll
        for (int u = 0; u < 4; u++) {
            xiA[u] = *(const float2*)(sXI + ii * FDIM + u * 16 + 2 * q);
            xiB[u] = *(const float2*)(sXI + ii * FDIM + u * 16 + 2 * q + 8);
        }

        float D[16];
#pragma unroll
        for (int z = 0; z < 16; z++) D[z] = 0.0f;

#pragma unroll
        for (int s = 0; s < 8; s++) {
            int u = s & 3;
            uint32_t a0, a1, a2, a3;
            if (s < 4) {   // |xi - xj| block (K 0..63)
                a0 = pack_h2(fabsf(xiA[u].x - xjA0[u].x), fabsf(xiA[u].y - xjA0[u].y));
                a1 = pack_h2(fabsf(xiA[u].x - xjA1[u].x), fabsf(xiA[u].y - xjA1[u].y));
                a2 = pack_h2(fabsf(xiB[u].x - xjB0[u].x), fabsf(xiB[u].y - xjB0[u].y));
                a3 = pack_h2(fabsf(xiB[u].x - xjB1[u].x), fabsf(xiB[u].y - xjB1[u].y));
            } else {       // xi * xj block (K 64..127)
                a0 = pack_h2(xiA[u].x * xjA0[u].x, xiA[u].y * xjA0[u].y);
                a1 = pack_h2(xiA[u].x * xjA1[u].x, xiA[u].y * xjA1[u].y);
                a2 = pack_h2(xiB[u].x * xjB0[u].x, xiB[u].y * xjB0[u].y);
                a3 = pack_h2(xiB[u].x * xjB1[u].x, xiB[u].y * xjB1[u].y);
            }
            mma_f16(D + 0,  a0, a1, a2, a3, bf[s][0], bf[s][4]);
            mma_f16(D + 4,  a0, a1, a2, a3, bf[s][1], bf[s][5]);
            mma_f16(D + 8,  a0, a1, a2, a3, bf[s][2], bf[s][6]);
            mma_f16(D + 12, a0, a1, a2, a3, bf[s][3], bf[s][7]);
        }

        // ---- epilogue: add per-node terms, ReLU, W2 dot, quad reduce ----
        float p0 = 0.0f, p1 = 0.0f;
#pragma unroll
        for (int nt = 0; nt < 4; nt++) {
            float2 aiv = *(const float2*)(sA + ii * HID + nt * 8 + 2 * q);
            p0 += fmaxf(D[nt * 4 + 0] + aiv.x + bj0[2 * nt],     0.0f) * w2l[2 * nt];
            p0 += fmaxf(D[nt * 4 + 1] + aiv.y + bj0[2 * nt + 1], 0.0f) * w2l[2 * nt + 1];
            p1 += fmaxf(D[nt * 4 + 2] + aiv.x + bj1[2 * nt],     0.0f) * w2l[2 * nt];
            p1 += fmaxf(D[nt * 4 + 3] + aiv.y + bj1[2 * nt + 1], 0.0f) * w2l[2 * nt + 1];
        }
        p0 += __shfl_xor_sync(0xFFFFFFFF, p0, 1);
        p0 += __shfl_xor_sync(0xFFFFFFFF, p0, 2);
        p1 += __shfl_xor_sync(0xFFFFFFFF, p1, 1);
        p1 += __shfl_xor_sync(0xFFFFFFFF, p1, 2);
        if (q == 0) {
            P[(i0 + ii) * NODES + j0 + jr0] = sigmoid_f(p0 + b2v);
            P[(i0 + ii) * NODES + j0 + jr1] = sigmoid_f(p1 + b2v);
        }
    }
}

// ======================= sparse edge branch (fp32, exact) =======================
__device__ __forceinline__ unsigned long long pack2(float lo, float hi) {
    unsigned long long r;
    asm("mov.b64 %0, {%1, %2};" : "=l"(r) : "f"(lo), "f"(hi));
    return r;
}
__device__ __forceinline__ void unpack2(unsigned long long v, float& lo, float& hi) {
    asm("mov.b64 {%0, %1}, %2;" : "=f"(lo), "=f"(hi) : "l"(v));
}
__device__ __forceinline__ unsigned long long ffma2(unsigned long long a,
                                                    unsigned long long b,
                                                    unsigned long long c) {
    unsigned long long d;
    asm("fma.rn.f32x2 %0, %1, %2, %3;" : "=l"(d) : "l"(a), "l"(b), "l"(c));
    return d;
}

__global__ __launch_bounds__(256)
void edge_kernel(const float* __restrict__ x,
                 const int* __restrict__ ei,   // int32 (JAX x64 disabled)
                 const float* __restrict__ W1,
                 const float* __restrict__ W2,
                 const float* __restrict__ b2,
                 float* __restrict__ probs,
                 float* __restrict__ acts) {
    __shared__ unsigned long long s_Wc[FDIM][HH];
    __shared__ unsigned long long s_Wd[FDIM][HH];
    __shared__ float s_W2[HID];
    int t = threadIdx.x;
    for (int k = t; k < FDIM * HH; k += 256) {
        int f = k >> 4, hh = k & 15;
        float2 c = ((const float2*)(W1 + (128 + f) * HID))[hh];
        float2 d = ((const float2*)(W1 + (192 + f) * HID))[hh];
        s_Wc[f][hh] = pack2(c.x, c.y);
        s_Wd[f][hh] = pack2(d.x, d.y);
    }
    if (t < HID) s_W2[t] = W2[t];
    __syncthreads();

    int e = blockIdx.x * 256 + t;
    int s = ei[e];
    int d = ei[EDGES + e];

    unsigned long long acc[HH];
    {
        const float* Ar = g_A + s * HID;
        const float* Br = g_B + d * HID;
#pragma unroll
        for (int hh = 0; hh < HH; hh++)
            acc[hh] = pack2(Ar[2 * hh] + Br[2 * hh], Ar[2 * hh + 1] + Br[2 * hh + 1]);
    }

    const float4* xs4 = (const float4*)(x + s * FDIM);
    const float4* xd4 = (const float4*)(x + d * FDIM);
#pragma unroll 4
    for (int c = 0; c < FDIM / 4; c++) {
        float4 a = __ldg(xs4 + c);
        float4 b = __ldg(xd4 + c);
        float av[4] = {a.x, a.y, a.z, a.w};
        float bv[4] = {b.x, b.y, b.z, b.w};
#pragma unroll
        for (int u = 0; u < 4; u++) {
            int f = c * 4 + u;
            float ad = fabsf(av[u] - bv[u]);
            float pr = av[u] * bv[u];
            unsigned long long dd = pack2(ad, ad);
            unsigned long long pm = pack2(pr, pr);
#pragma unroll
            for (int hh = 0; hh < HH; hh++) {
                acc[hh] = ffma2(dd, s_Wc[f][hh], acc[hh]);
                acc[hh] = ffma2(pm, s_Wd[f][hh], acc[hh]);
            }
        }
    }

    float logit = b2[0];
#pragma unroll
    for (int hh = 0; hh < HH; hh++) {
        float lo, hi;
        unpack2(acc[hh], lo, hi);
        logit += fmaxf(lo, 0.0f) * s_W2[2 * hh] + fmaxf(hi, 0.0f) * s_W2[2 * hh + 1];
    }
    float prob = 1.0f / (1.0f + expf(-logit));
    probs[e] = prob;
    acts[e]  = (prob > 0.4f) ? 1.0f : 0.0f;
}

// ======================= launch =======================
extern "C" void kernel_launch(void* const* d_in, const int* in_sizes, int n_in,
                              void* d_out, int out_size) {
    const float* x  = (const float*)d_in[0];
    const int*   ei = (const int*)d_in[1];     // int32 (JAX x64 disabled)
    const float* W1 = (const float*)d_in[3];
    const float* b1 = (const float*)d_in[4];
    const float* W2 = (const float*)d_in[5];
    const float* b2 = (const float*)d_in[6];

    float* out   = (float*)d_out;
    float* probs = out;
    float* acts  = out + EDGES;
    float* P     = out + 2 * EDGES;

    static int smem_set = 0;
    if (!smem_set) {
        cudaFuncSetAttribute(dense_mma_kernel,
                             cudaFuncAttributeMaxDynamicSharedMemorySize,
                             DENSE_SMEM_F * 4);
        smem_set = 1;
    }

    prep_kernel<<<NODES / 4, 256>>>(x, W1, b1);
    edge_kernel<<<EDGES / 256, 256>>>(x, ei, W1, W2, b2, probs, acts);
    dim3 grid(NODES / BI, NODES / BJ);
    dense_mma_kernel<<<grid, 256, DENSE_SMEM_F * 4>>>(x, W1, W2, b2, P);
}

// round 13
// speedup vs baseline: 3.1122x; 1.0818x over previous
#include <cuda_runtime.h>
#include <math.h>
#include <stdint.h>

#define NODES 1024
#define FDIM  64
#define HID   32
#define HH    16
#define EDGES 65536
#define BI    32     // i-rows per dense CTA
#define BJ    128    // j-cols per dense CTA (8 warps x 16)

// Precomputed per-node terms: A = x @ W1[0:64] + b1 ; B = x @ W1[64:128]
__device__ float g_A[NODES * HID];
__device__ float g_B[NODES * HID];

__device__ __forceinline__ float sigmoid_f(float v) {
    return 1.0f / (1.0f + expf(-v));
}

// ======================= prep: per-node A/B =======================
__global__ void prep_kernel(const float* __restrict__ x,
                            const float* __restrict__ W1,
                            const float* __restrict__ b1) {
    __shared__ float xr[4][FDIM];
    int t = threadIdx.x;                     // 256
    int nl = t >> 6, s = t & 63;
    int node = blockIdx.x * 4 + nl;
    xr[nl][s] = x[node * FDIM + s];
    __syncthreads();
    int h = s & 31;
    const float* W = W1 + ((s < 32) ? 0 : FDIM * HID);
    float acc = (s < 32) ? b1[h] : 0.0f;
#pragma unroll
    for (int f = 0; f < FDIM; f++)
        acc = fmaf(xr[nl][f], W[f * HID + h], acc);
    if (s < 32) g_A[node * HID + h] = acc;
    else        g_B[node * HID + h] = acc;
}

// ======================= dense all-pairs: mma.sync fp16, f16x2 feature gen =======================
// smem u32 layout:
//   sW    [8][32][8]        = 2048 u32
//   sXJ16 [128][34] (pad)   = 4352 u32
//   sXI16 [32][34]  (pad)   = 1088 u32
//   sA    [32][32] f32      = 1024 u32
#define SW_OFF   0
#define SXJ_OFF  2048
#define SXI_OFF  (2048 + 4352)
#define SA_OFF   (2048 + 4352 + 1088)
#define DENSE_SMEM_U (2048 + 4352 + 1088 + 1024)
#define XJP 34
#define XIP 34

// pack two f32 -> f16x2 (lo in lower half)
__device__ __forceinline__ uint32_t pack_h2(float lo, float hi) {
    uint32_t r;
    asm("cvt.rn.f16x2.f32 %0, %1, %2;" : "=r"(r) : "f"(hi), "f"(lo));
    return r;
}
__device__ __forceinline__ uint32_t hsub2(uint32_t a, uint32_t b) {
    uint32_t r;
    asm("sub.f16x2 %0, %1, %2;" : "=r"(r) : "r"(a), "r"(b));
    return r;
}
__device__ __forceinline__ uint32_t habs2(uint32_t a) {
    return a & 0x7FFF7FFFu;
}
__device__ __forceinline__ uint32_t hmul2(uint32_t a, uint32_t b) {
    uint32_t r;
    asm("mul.f16x2 %0, %1, %2;" : "=r"(r) : "r"(a), "r"(b));
    return r;
}

__device__ __forceinline__ void mma_f16(float* D, uint32_t a0, uint32_t a1,
                                        uint32_t a2, uint32_t a3,
                                        uint32_t b0, uint32_t b1) {
    asm volatile(
        "mma.sync.aligned.m16n8k16.row.col.f32.f16.f16.f32 "
        "{%0,%1,%2,%3}, {%4,%5,%6,%7}, {%8,%9}, {%0,%1,%2,%3};"
        : "+f"(D[0]), "+f"(D[1]), "+f"(D[2]), "+f"(D[3])
        : "r"(a0), "r"(a1), "r"(a2), "r"(a3), "r"(b0), "r"(b1));
}

__global__ __launch_bounds__(256, 1)
void dense_mma_kernel(const float* __restrict__ x,
                      const float* __restrict__ W1,
                      const float* __restrict__ W2,
                      const float* __restrict__ b2,
                      float* __restrict__ P) {
    extern __shared__ uint32_t smu[];
    uint32_t* sW    = smu + SW_OFF;      // [8 steps][32 lanes][8]
    uint32_t* sXJ16 = smu + SXJ_OFF;     // [128][34] f16x2 (feat pair per u32)
    uint32_t* sXI16 = smu + SXI_OFF;     // [32][34]
    float*    sA    = (float*)(smu + SA_OFF);  // [32][32]

    int t  = threadIdx.x;
    int i0 = blockIdx.x * BI;
    int j0 = blockIdx.y * BJ;

    // ---- stage xj block as f16x2 ----
    for (int k = t; k < BJ * 16; k += 256) {      // 16 float4 per row
        int row = k >> 4, c4 = k & 15;
        float4 v = __ldg((const float4*)(x + (j0 + row) * FDIM) + c4);
        sXJ16[row * XJP + c4 * 2]     = pack_h2(v.x, v.y);
        sXJ16[row * XJP + c4 * 2 + 1] = pack_h2(v.z, v.w);
    }
    // ---- stage xi block as f16x2 ----
    for (int k = t; k < BI * 16; k += 256) {
        int row = k >> 4, c4 = k & 15;
        float4 v = __ldg((const float4*)(x + (i0 + row) * FDIM) + c4);
        sXI16[row * XIP + c4 * 2]     = pack_h2(v.x, v.y);
        sXI16[row * XIP + c4 * 2 + 1] = pack_h2(v.z, v.w);
    }
    // ---- stage A_i ----
    for (int k = t; k < BI * HID; k += 256)
        sA[k] = g_A[(i0 + (k >> 5)) * HID + (k & 31)];
    // ---- prepack B fragments (W1 rows 128..255 -> f16x2, per-lane layout) ----
    for (int g = t; g < 8 * 32; g += 256) {
        int s = g >> 5, ln = g & 31;
        int qq = ln & 3, rr = ln >> 2;
        uint32_t* dst = sW + (s * 32 + ln) * 8;
        int kb = s * 16;
#pragma unroll
        for (int nt = 0; nt < 4; nt++) {
            int n = nt * 8 + rr;
            int f0 = kb + 2 * qq;
            int f2 = kb + 2 * qq + 8;
            float w00 = W1[(128 + f0) * HID + n];
            float w01 = W1[(128 + f0 + 1) * HID + n];
            float w20 = W1[(128 + f2) * HID + n];
            float w21 = W1[(128 + f2 + 1) * HID + n];
            dst[nt]     = pack_h2(w00, w01);
            dst[4 + nt] = pack_h2(w20, w21);
        }
    }
    __syncthreads();

    int lane = t & 31, wid = t >> 5;
    int q = lane & 3, r = lane >> 2;
    int jr0 = wid * 16 + r;        // D rows 0..7  -> j index
    int jr1 = jr0 + 8;             // D rows 8..15 -> j index

    // ---- hoist all B fragments to registers: 8 steps x 8 u32 = 64 regs ----
    uint32_t bf[8][8];
#pragma unroll
    for (int s = 0; s < 8; s++) {
        const uint32_t* bp = sW + (s * 32 + lane) * 8;
        float4 v0 = *(const float4*)bp;
        float4 v1 = *(const float4*)(bp + 4);
        bf[s][0] = __float_as_uint(v0.x); bf[s][1] = __float_as_uint(v0.y);
        bf[s][2] = __float_as_uint(v0.z); bf[s][3] = __float_as_uint(v0.w);
        bf[s][4] = __float_as_uint(v1.x); bf[s][5] = __float_as_uint(v1.y);
        bf[s][6] = __float_as_uint(v1.z); bf[s][7] = __float_as_uint(v1.w);
    }

    // ---- xj register cache (f16x2): u32 idx u*8+q (pair A) / u*8+q+4 (pair B) ----
    uint32_t xjA0[4], xjB0[4], xjA1[4], xjB1[4];
#pragma unroll
    for (int u = 0; u < 4; u++) {
        xjA0[u] = sXJ16[jr0 * XJP + u * 8 + q];
        xjB0[u] = sXJ16[jr0 * XJP + u * 8 + q + 4];
        xjA1[u] = sXJ16[jr1 * XJP + u * 8 + q];
        xjB1[u] = sXJ16[jr1 * XJP + u * 8 + q + 4];
    }

    // epilogue constants
    float bj0[8], bj1[8], w2l[8];
#pragma unroll
    for (int nt = 0; nt < 4; nt++) {
        int h = nt * 8 + 2 * q;
        bj0[2 * nt]     = g_B[(j0 + jr0) * HID + h];
        bj0[2 * nt + 1] = g_B[(j0 + jr0) * HID + h + 1];
        bj1[2 * nt]     = g_B[(j0 + jr1) * HID + h];
        bj1[2 * nt + 1] = g_B[(j0 + jr1) * HID + h + 1];
        w2l[2 * nt]     = __ldg(W2 + h);
        w2l[2 * nt + 1] = __ldg(W2 + h + 1);
    }
    float b2v = __ldg(b2);

    for (int ii = 0; ii < BI; ii++) {
        uint32_t xiA[4], xiB[4];
#pragma unroll
        for (int u = 0; u < 4; u++) {
            xiA[u] = sXI16[ii * XIP + u * 8 + q];        // broadcast within quad
            xiB[u] = sXI16[ii * XIP + u * 8 + q + 4];
        }

        float D[16];
#pragma unroll
        for (int z = 0; z < 16; z++) D[z] = 0.0f;

#pragma unroll
        for (int s = 0; s < 8; s++) {
            int u = s & 3;
            uint32_t a0, a1, a2, a3;
            if (s < 4) {   // |xi - xj| block (K 0..63)
                a0 = habs2(hsub2(xiA[u], xjA0[u]));
                a1 = habs2(hsub2(xiA[u], xjA1[u]));
                a2 = habs2(hsub2(xiB[u], xjB0[u]));
                a3 = habs2(hsub2(xiB[u], xjB1[u]));
            } else {       // xi * xj block (K 64..127)
                a0 = hmul2(xiA[u], xjA0[u]);
                a1 = hmul2(xiA[u], xjA1[u]);
                a2 = hmul2(xiB[u], xjB0[u]);
                a3 = hmul2(xiB[u], xjB1[u]);
            }
            mma_f16(D + 0,  a0, a1, a2, a3, bf[s][0], bf[s][4]);
            mma_f16(D + 4,  a0, a1, a2, a3, bf[s][1], bf[s][5]);
            mma_f16(D + 8,  a0, a1, a2, a3, bf[s][2], bf[s][6]);
            mma_f16(D + 12, a0, a1, a2, a3, bf[s][3], bf[s][7]);
        }

        // ---- epilogue: add per-node terms, ReLU, W2 dot, quad reduce ----
        float p0 = 0.0f, p1 = 0.0f;
#pragma unroll
        for (int nt = 0; nt < 4; nt++) {
            float2 aiv = *(const float2*)(sA + ii * HID + nt * 8 + 2 * q);
            p0 += fmaxf(D[nt * 4 + 0] + aiv.x + bj0[2 * nt],     0.0f) * w2l[2 * nt];
            p0 += fmaxf(D[nt * 4 + 1] + aiv.y + bj0[2 * nt + 1], 0.0f) * w2l[2 * nt + 1];
            p1 += fmaxf(D[nt * 4 + 2] + aiv.x + bj1[2 * nt],     0.0f) * w2l[2 * nt];
            p1 += fmaxf(D[nt * 4 + 3] + aiv.y + bj1[2 * nt + 1], 0.0f) * w2l[2 * nt + 1];
        }
        p0 += __shfl_xor_sync(0xFFFFFFFF, p0, 1);
        p0 += __shfl_xor_sync(0xFFFFFFFF, p0, 2);
        p1 += __shfl_xor_sync(0xFFFFFFFF, p1, 1);
        p1 += __shfl_xor_sync(0xFFFFFFFF, p1, 2);
        if (q == 0) {
            P[(i0 + ii) * NODES + j0 + jr0] = sigmoid_f(p0 + b2v);
            P[(i0 + ii) * NODES + j0 + jr1] = sigmoid_f(p1 + b2v);
        }
    }
}

// ======================= sparse edge branch (fp32, exact) =======================
__device__ __forceinline__ unsigned long long pack2(float lo, float hi) {
    unsigned long long r;
    asm("mov.b64 %0, {%1, %2};" : "=l"(r) : "f"(lo), "f"(hi));
    return r;
}
__device__ __forceinline__ void unpack2(unsigned long long v, float& lo, float& hi) {
    asm("mov.b64 {%0, %1}, %2;" : "=f"(lo), "=f"(hi) : "l"(v));
}
__device__ __forceinline__ unsigned long long ffma2(unsigned long long a,
                                                    unsigned long long b,
                                                    unsigned long long c) {
    unsigned long long d;
    asm("fma.rn.f32x2 %0, %1, %2, %3;" : "=l"(d) : "l"(a), "l"(b), "l"(c));
    return d;
}

__global__ __launch_bounds__(256)
void edge_kernel(const float* __restrict__ x,
                 const int* __restrict__ ei,   // int32 (JAX x64 disabled)
                 const float* __restrict__ W1,
                 const float* __restrict__ W2,
                 const float* __restrict__ b2,
                 float* __restrict__ probs,
                 float* __restrict__ acts) {
    __shared__ unsigned long long s_Wc[FDIM][HH];
    __shared__ unsigned long long s_Wd[FDIM][HH];
    __shared__ float s_W2[HID];
    int t = threadIdx.x;
    for (int k = t; k < FDIM * HH; k += 256) {
        int f = k >> 4, hh = k & 15;
        float2 c = ((const float2*)(W1 + (128 + f) * HID))[hh];
        float2 d = ((const float2*)(W1 + (192 + f) * HID))[hh];
        s_Wc[f][hh] = pack2(c.x, c.y);
        s_Wd[f][hh] = pack2(d.x, d.y);
    }
    if (t < HID) s_W2[t] = W2[t];
    __syncthreads();

    int e = blockIdx.x * 256 + t;
    int s = ei[e];
    int d = ei[EDGES + e];

    unsigned long long acc[HH];
    {
        const float* Ar = g_A + s * HID;
        const float* Br = g_B + d * HID;
#pragma unroll
        for (int hh = 0; hh < HH; hh++)
            acc[hh] = pack2(Ar[2 * hh] + Br[2 * hh], Ar[2 * hh + 1] + Br[2 * hh + 1]);
    }

    const float4* xs4 = (const float4*)(x + s * FDIM);
    const float4* xd4 = (const float4*)(x + d * FDIM);
#pragma unroll 4
    for (int c = 0; c < FDIM / 4; c++) {
        float4 a = __ldg(xs4 + c);
        float4 b = __ldg(xd4 + c);
        float av[4] = {a.x, a.y, a.z, a.w};
        float bv[4] = {b.x, b.y, b.z, b.w};
#pragma unroll
        for (int u = 0; u < 4; u++) {
            int f = c * 4 + u;
            float ad = fabsf(av[u] - bv[u]);
            float pr = av[u] * bv[u];
            unsigned long long dd = pack2(ad, ad);
            unsigned long long pm = pack2(pr, pr);
#pragma unroll
            for (int hh = 0; hh < HH; hh++) {
                acc[hh] = ffma2(dd, s_Wc[f][hh], acc[hh]);
                acc[hh] = ffma2(pm, s_Wd[f][hh], acc[hh]);
            }
        }
    }

    float logit = b2[0];
#pragma unroll
    for (int hh = 0; hh < HH; hh++) {
        float lo, hi;
        unpack2(acc[hh], lo, hi);
        logit += fmaxf(lo, 0.0f) * s_W2[2 * hh] + fmaxf(hi, 0.0f) * s_W2[2 * hh + 1];
    }
    float prob = 1.0f / (1.0f + expf(-logit));
    probs[e] = prob;
    acts[e]  = (prob > 0.4f) ? 1.0f : 0.0f;
}

// ======================= launch =======================
extern "C" void kernel_launch(void* const* d_in, const int* in_sizes, int n_in,
                              void* d_out, int out_size) {
    const float* x  = (const float*)d_in[0];
    const int*   ei = (const int*)d_in[1];     // int32 (JAX x64 disabled)
    const float* W1 = (const float*)d_in[3];
    const float* b1 = (const float*)d_in[4];
    const float* W2 = (const float*)d_in[5];
    const float* b2 = (const float*)d_in[6];

    float* out   = (float*)d_out;
    float* probs = out;
    float* acts  = out + EDGES;
    float* P     = out + 2 * EDGES;

    static int smem_set = 0;
    if (!smem_set) {
        cudaFuncSetAttribute(dense_mma_kernel,
                             cudaFuncAttributeMaxDynamicSharedMemorySize,
                             DENSE_SMEM_U * 4);
        smem_set = 1;
    }

    prep_kernel<<<NODES / 4, 256>>>(x, W1, b1);
    edge_kernel<<<EDGES / 256, 256>>>(x, ei, W1, W2, b2, probs, acts);
    dim3 grid(NODES / BI, NODES / BJ);
    dense_mma_kernel<<<grid, 256, DENSE_SMEM_U * 4>>>(x, W1, W2, b2, P);
}